// round 8
// baseline (speedup 1.0000x reference)
#include <cuda_runtime.h>
#include <cstdint>

#define BATCH 16
#define NA    8400
#define NC    80
#define NM    24
#define KTOP  13
#define REG   16
#define CH    256
#define CHUNKS 33   // ceil(8400/256)

// ---------------- device scratch ----------------
__device__ unsigned long long g_best[BATCH * NA];
__device__ unsigned long long g_cand[BATCH * NM * CHUNKS * KTOP];
__device__ float g_mx[BATCH * NA];
__device__ float g_cmask[BATCH * NC];
__device__ int   g_lab[BATCH * NM];
__device__ int   g_val[BATCH * NM];
__device__ float g_partial[BATCH][CHUNKS][8];
__device__ int   g_ctr_main[BATCH];           // zero-init; self-resetting
__device__ int   g_ctr_loss;                  // zero-init; self-resetting

// ---------------- helpers ----------------
__device__ __forceinline__ float sigmoidf(float x) { return 1.0f / (1.0f + expf(-x)); }

__device__ __forceinline__ float iou_box(float a0, float a1, float a2, float a3,
                                         float b0, float b1, float b2, float b3) {
    float lt0 = fmaxf(a0, b0), lt1 = fmaxf(a1, b1);
    float rb0 = fminf(a2, b2), rb1 = fminf(a3, b3);
    float w = fmaxf(rb0 - lt0, 0.0f), h = fmaxf(rb1 - lt1, 0.0f);
    float inter = w * h;
    float aa = fmaxf(a2 - a0, 0.0f) * fmaxf(a3 - a1, 0.0f);
    float ab = fmaxf(b2 - b0, 0.0f) * fmaxf(b3 - b1, 0.0f);
    return inter / (aa + ab - inter + 1e-7f);
}

__device__ __forceinline__ float load_cmask_raw(const void* cm, int cmode, int i) {
    float v;
    if (cmode == 0)      v = ((const float*)cm)[i];
    else if (cmode == 1) v = (float)(((const int*)cm)[i] != 0);
    else                 v = (float)(((const unsigned char*)cm)[i] != 0);
    return (v != 0.0f) ? 1.0f : 0.0f;
}

// ============ k_prep: one block, parallel dtype detect + normalize ============
__global__ __launch_bounds__(256) void k_prep(const void* __restrict__ cm,
                                              const void* __restrict__ lab) {
    __shared__ int flag_c, flag_l;
    int t = threadIdx.x;
    if (t == 0) { flag_c = 0; flag_l = 0; }
    __syncthreads();

    const unsigned* cw = (const unsigned*)cm;
    if (t < 80 && cw[t] > 1u) atomicOr(&flag_c, 1);
    const unsigned* lw = (const unsigned*)lab;
    for (int i = t; i < BATCH * NM; i += 256)
        if (lw[i] > 1000u) atomicOr(&flag_l, 1);
    __syncthreads();

    int cmode = (cw[0] == 0x3F800000u) ? 0 : (flag_c ? 2 : 1);
    int lmode = flag_l;

    for (int i = t; i < BATCH * NC; i += 256)
        g_cmask[i] = load_cmask_raw(cm, cmode, i);
    for (int i = t; i < BATCH * NM; i += 256) {
        int lb = lmode ? (int)(((const float*)lab)[i]) : ((const int*)lab)[i];
        int labc = min(max(lb, 0), NC - 1);
        int b = i / NM;
        g_lab[i] = labc;
        g_val[i] = (lb >= 0 && lb < NC) &&
                   (load_cmask_raw(cm, cmode, b * NC + labc) != 0.0f);
    }
}

// ============ k_main: masked max + align + local top-13 + (last block) merge/scatter ============
__global__ __launch_bounds__(256) void k_main(const float* __restrict__ pb,
                                              const float* __restrict__ ps,
                                              const float* __restrict__ ap,
                                              const float* __restrict__ gtb) {
    __shared__ float4 cm4_s[20];
    __shared__ int   lab_s[NM];
    __shared__ int   val_s[NM];
    __shared__ float4 gtb_s[NM];
    __shared__ float pm[8][32][21];
    __shared__ float align_s[NM][CH + 1];
    __shared__ int   is_last;

    int chunk = blockIdx.x, b = blockIdx.y, t = threadIdx.x;
    int lane = t & 31, w = t >> 5;
    int nbase = chunk * CH;

    if (t < 20) cm4_s[t] = ((const float4*)(g_cmask + b * NC))[t];
    if (t < NM) {
        lab_s[t] = g_lab[b * NM + t];
        val_s[t] = g_val[b * NM + t];
        gtb_s[t] = ((const float4*)gtb)[b * NM + t];
    }
#pragma unroll 4
    for (int g = 0; g < NM; g++) align_s[g][t] = -1.0f;
    if (nbase + t < NA) g_best[b * NA + nbase + t] = 0ull;
    __syncthreads();

    int a0 = nbase + w * 32;
    int alim = min(32, NA - a0);          // warp-uniform

    // Phase A: coalesced score read, lane-partial masked max -> smem.
    // Full-warp case fully unrolled: 32 independent LDG.128s in flight.
    if (lane < 20 && alim > 0) {
        const float4* row4 = (const float4*)(ps + ((size_t)b * NA + a0) * NC);
        float4 m4 = cm4_s[lane];
        if (alim == 32) {
#pragma unroll
            for (int a = 0; a < 32; a++) {
                float4 s4 = row4[(size_t)a * 20 + lane];
                float m = -1e30f;
                m = fmaxf(m, m4.x != 0.0f ? s4.x : -1e30f);
                m = fmaxf(m, m4.y != 0.0f ? s4.y : -1e30f);
                m = fmaxf(m, m4.z != 0.0f ? s4.z : -1e30f);
                m = fmaxf(m, m4.w != 0.0f ? s4.w : -1e30f);
                pm[w][a][lane] = m;
            }
        } else {
            for (int a = 0; a < alim; a++) {
                float4 s4 = row4[(size_t)a * 20 + lane];
                float m = -1e30f;
                m = fmaxf(m, m4.x != 0.0f ? s4.x : -1e30f);
                m = fmaxf(m, m4.y != 0.0f ? s4.y : -1e30f);
                m = fmaxf(m, m4.z != 0.0f ? s4.z : -1e30f);
                m = fmaxf(m, m4.w != 0.0f ? s4.w : -1e30f);
                pm[w][a][lane] = m;
            }
        }
    }
    __syncwarp();

    // Phase B: per-lane reduce own anchor's 20 partials, coalesced store
    if (lane < alim) {
        float m = -1e30f;
#pragma unroll
        for (int j = 0; j < 20; j++) m = fmaxf(m, pm[w][lane][j]);
        g_mx[b * NA + a0 + lane] = m;
    }

    // Phase C: align; lane owns anchor, loop GTs
    int n = a0 + lane;
    if (n < NA && alim > 0) {
        float2 apc = ((const float2*)ap)[n];
        float4 pbx = ((const float4*)pb)[(size_t)b * NA + n];
        const float* srow = ps + ((size_t)b * NA + n) * NC;
#pragma unroll 4
        for (int g = 0; g < NM; g++) {
            float4 gbx = gtb_s[g];
            bool inside = val_s[g] && apc.x >= gbx.x && apc.x <= gbx.z &&
                          apc.y >= gbx.y && apc.y <= gbx.w;
            if (inside) {
                float iou = iou_box(pbx.x, pbx.y, pbx.z, pbx.w, gbx.x, gbx.y, gbx.z, gbx.w);
                float cls = sigmoidf(srow[lab_s[g]]);
                float i2 = iou * iou;
                align_s[g][w * 32 + lane] = cls * (i2 * i2 * i2);
            }
        }
    }
    __syncthreads();

    // Phase D: local top-13; warp w handles GTs w, w+8, w+16
#pragma unroll
    for (int gi = 0; gi < 3; gi++) {
        int g = w + gi * 8;
        unsigned long long key[8];
        unsigned ball[8];
        int base[8], tot = 0;
#pragma unroll
        for (int r = 0; r < 8; r++) {
            float v = align_s[g][lane + 32 * r];
            int nn = nbase + lane + 32 * r;
            key[r] = (v >= 0.0f)
                ? (((unsigned long long)__float_as_uint(v) << 32) | (unsigned)(0xFFFFFFFFu - nn))
                : 0ull;
            ball[r] = __ballot_sync(~0u, key[r] != 0ull);
            base[r] = tot;
            tot += __popc(ball[r]);
        }
        unsigned long long* outc = g_cand + (((size_t)b * NM + g) * CHUNKS + chunk) * KTOP;

        if (tot <= KTOP) {
            unsigned lt = (1u << lane) - 1u;
#pragma unroll
            for (int r = 0; r < 8; r++) {
                if (key[r] != 0ull) {
                    int slot = base[r] + __popc(ball[r] & lt);
                    outc[slot] = key[r];
                }
            }
            if (lane >= tot && lane < KTOP) outc[lane] = 0ull;
        } else {
            for (int k = 0; k < KTOP; k++) {
                unsigned long long lm = key[0]; int lr = 0;
#pragma unroll
                for (int r = 1; r < 8; r++) if (key[r] > lm) { lm = key[r]; lr = r; }
                unsigned long long wm = lm;
#pragma unroll
                for (int o = 16; o > 0; o >>= 1) {
                    unsigned long long oth = __shfl_xor_sync(~0u, wm, o);
                    if (oth > wm) wm = oth;
                }
                if (lm == wm) key[lr] = 0ull;
                if (lane == 0) outc[k] = wm;
            }
        }
    }

    // ---- last block of this batch: merge + scatter ----
    __threadfence();
    __syncthreads();
    if (t == 0) is_last = (atomicAdd(&g_ctr_main[b], 1) == CHUNKS - 1);
    __syncthreads();
    if (!is_last) return;
    if (t == 0) g_ctr_main[b] = 0;
    __threadfence();

#pragma unroll
    for (int gi = 0; gi < 3; gi++) {
        int g = w + gi * 8;
        const unsigned long long* src = g_cand + ((size_t)b * NM + g) * CHUNKS * KTOP;
        unsigned long long key[14];
#pragma unroll
        for (int r = 0; r < 14; r++) {
            int e = lane + 32 * r;
            key[r] = (e < CHUNKS * KTOP) ? src[e] : 0ull;
        }
        unsigned pri = (unsigned)(NM - g);
        for (int k = 0; k < KTOP; k++) {
            unsigned long long lm = key[0]; int lr = 0;
#pragma unroll
            for (int r = 1; r < 14; r++) if (key[r] > lm) { lm = key[r]; lr = r; }
            unsigned long long wm = lm;
#pragma unroll
            for (int o = 16; o > 0; o >>= 1) {
                unsigned long long oth = __shfl_xor_sync(~0u, wm, o);
                if (oth > wm) wm = oth;
            }
            if (wm == 0ull) break;
            if (lm == wm) {
                key[lr] = 0ull;
                int nn = (int)(0xFFFFFFFFu - (unsigned)(wm & 0xFFFFFFFFull));
                unsigned long long key2 = (wm & 0xFFFFFFFF00000000ull) | pri;
                atomicMax(&g_best[b * NA + nn], key2);
            }
        }
    }
}

// ============ k_loss: light terms + deterministic fg compaction + warp-coop heavy + final ============
__global__ __launch_bounds__(256) void k_loss(const float* __restrict__ pb,
                                              const float* __restrict__ ps,
                                              const float* __restrict__ pobj,
                                              const float* __restrict__ ap,
                                              const float* __restrict__ st,
                                              const float* __restrict__ bd,
                                              const float* __restrict__ gtb,
                                              float* __restrict__ out) {
    __shared__ float4 cm4_s[20];
    __shared__ float wred[8][8];
    __shared__ int   scnt[8];
    __shared__ int   sbase[9];
    __shared__ int   slist[CH];     // (n_local << 5) | g
    __shared__ int   is_last;
    __shared__ float img[BATCH][8];

    int b = blockIdx.y, t = threadIdx.x;
    int lane = t & 31, w = t >> 5;
    int nb0 = blockIdx.x * CH;
    int n = nb0 + t;

    if (t < 20) cm4_s[t] = ((const float4*)(g_cmask + b * NC))[t];

    // ---- light terms + fg detection ----
    float l_focal = 0.0f, l_cnt = 0.0f, l_neg = 0.0f;
    int my_g = 0;
    bool fg = false;
    if (n < NA) {
        unsigned long long key = g_best[b * NA + n];
        fg = (key != 0ull);
        float x = pobj[(size_t)b * NA + n];
        float tt = fg ? 1.0f : 0.0f;
        float ce_o = fmaxf(x, 0.0f) - x * tt + log1pf(expf(-fabsf(x)));
        float prob_o = sigmoidf(x);
        float p_t = fg ? prob_o : (1.0f - prob_o);
        float af  = fg ? 0.25f  : 0.75f;
        float om  = 1.0f - p_t;
        l_focal = ce_o * af * om * om;
        if (fg) { l_cnt = 1.0f; my_g = NM - (int)(key & 0xFFFFFFFFull); }
        else    l_neg = prob_o * sigmoidf(g_mx[b * NA + n]);
    }

    // deterministic compaction: per-warp ballot, warp-ordered bases
    unsigned ball = __ballot_sync(~0u, fg);
    if (lane == 0) scnt[w] = __popc(ball);
    __syncthreads();
    if (t == 0) {
        sbase[0] = 0;
#pragma unroll
        for (int ww = 0; ww < 8; ww++) sbase[ww + 1] = sbase[ww] + scnt[ww];
    }
    __syncthreads();
    int tot = sbase[8];
    if (fg) {
        int slot = sbase[w] + __popc(ball & ((1u << lane) - 1u));
        slist[slot] = (t << 5) | my_g;
    }
    __syncthreads();

    // ---- heavy terms: warp-cooperative, warps round-robin the fg list ----
    float ace = 0, aciou = 0, aiou = 0, apos = 0, adfl = 0;
    float4 m4 = (lane < 20) ? cm4_s[lane] : make_float4(0, 0, 0, 0);

    for (int i = w; i < tot; i += 8) {
        int e = slist[i];
        int nn = nb0 + (e >> 5);
        int g = e & 31;
        size_t off = (size_t)b * NA + nn;
        int lab = g_lab[b * NM + g];
        float4 gb4 = ((const float4*)gtb)[b * NM + g];
        float mx = g_mx[off];

        // masked LSE over 80 classes, 20 lanes, coalesced float4
        float4 s4 = (lane < 20) ? ((const float4*)(ps + off * NC))[lane]
                                : make_float4(0, 0, 0, 0);
        float es = 0.0f;
        es += (m4.x != 0.0f) ? expf(s4.x - mx) : 0.0f;
        es += (m4.y != 0.0f) ? expf(s4.y - mx) : 0.0f;
        es += (m4.z != 0.0f) ? expf(s4.z - mx) : 0.0f;
        es += (m4.w != 0.0f) ? expf(s4.w - mx) : 0.0f;
#pragma unroll
        for (int o = 16; o > 0; o >>= 1) es += __shfl_xor_sync(~0u, es, o);
        float lse = mx + logf(es);

        int sl = lab >> 2, sc = lab & 3;
        float c0 = __shfl_sync(~0u, s4.x, sl);
        float c1 = __shfl_sync(~0u, s4.y, sl);
        float c2v = __shfl_sync(~0u, s4.z, sl);
        float c3 = __shfl_sync(~0u, s4.w, sl);
        float slab = (sc == 0) ? c0 : (sc == 1) ? c1 : (sc == 2) ? c2v : c3;

        float prob_o = sigmoidf(pobj[off]);

        // IoU / CIoU (redundant across lanes, warp-uniform)
        float4 a4 = ((const float4*)pb)[off];
        float iou = iou_box(a4.x, a4.y, a4.z, a4.w, gb4.x, gb4.y, gb4.z, gb4.w);
        float cw = fmaxf(a4.z, gb4.z) - fminf(a4.x, gb4.x);
        float ch = fmaxf(a4.w, gb4.w) - fminf(a4.y, gb4.y);
        float c2 = cw * cw + ch * ch + 1e-7f;
        float dx = a4.x + a4.z - gb4.x - gb4.z;
        float dy = a4.y + a4.w - gb4.y - gb4.w;
        float rho2 = (dx * dx + dy * dy) * 0.25f;
        float w1 = a4.z - a4.x, h1 = a4.w - a4.y;
        float w2 = gb4.z - gb4.x, h2 = gb4.w - gb4.y;
        float dat = atanf(w2 / (h2 + 1e-7f)) - atanf(w1 / (h1 + 1e-7f));
        float v = (4.0f / (3.14159265358979323846f * 3.14159265358979323846f)) * dat * dat;
        float alpha = v / (v - iou + 1.0f + 1e-7f);
        float ciou = iou - rho2 / c2 - v * alpha;

        // DFL: 16 lanes hold 64 logits, 4-lane groups per bin
        float4 d4 = (lane < 16) ? ((const float4*)(bd + off * (4 * REG)))[lane]
                                : make_float4(0, 0, 0, 0);
        int j = (lane >> 2) & 3;
        float2 apc = ((const float2*)ap)[nn];
        float s = st[nn];
        float tj = (j == 0) ? (apc.x - gb4.x) / s :
                   (j == 1) ? (apc.y - gb4.y) / s :
                   (j == 2) ? (gb4.z - apc.x) / s :
                              (gb4.w - apc.y) / s;
        float tv = fminf(fmaxf(tj, 0.0f), (float)(REG - 1) - 0.01f);
        int tl = (int)tv;
        int tr = min(tl + 1, REG - 1);
        float wl = (float)tr - tv;
        float wr = 1.0f - wl;

        float lmax = fmaxf(fmaxf(d4.x, d4.y), fmaxf(d4.z, d4.w));
        lmax = fmaxf(lmax, __shfl_xor_sync(~0u, lmax, 1));
        lmax = fmaxf(lmax, __shfl_xor_sync(~0u, lmax, 2));
        float lsum = expf(d4.x - lmax) + expf(d4.y - lmax) +
                     expf(d4.z - lmax) + expf(d4.w - lmax);
        lsum += __shfl_xor_sync(~0u, lsum, 1);
        lsum += __shfl_xor_sync(~0u, lsum, 2);
        float lse2 = lmax + logf(lsum);

        int baseL = lane & ~3;
        int stl = baseL + (tl >> 2), str_ = baseL + (tr >> 2);
        float tlx = __shfl_sync(~0u, d4.x, stl), tly = __shfl_sync(~0u, d4.y, stl);
        float tlz = __shfl_sync(~0u, d4.z, stl), tlw = __shfl_sync(~0u, d4.w, stl);
        int cl = tl & 3;
        float vtl = (cl == 0) ? tlx : (cl == 1) ? tly : (cl == 2) ? tlz : tlw;
        float trx = __shfl_sync(~0u, d4.x, str_), try_ = __shfl_sync(~0u, d4.y, str_);
        float trz = __shfl_sync(~0u, d4.z, str_), trw = __shfl_sync(~0u, d4.w, str_);
        int cr = tr & 3;
        float vtr = (cr == 0) ? trx : (cr == 1) ? try_ : (cr == 2) ? trz : trw;
        float dbin = (lse2 - vtl) * wl + (lse2 - vtr) * wr;
        float dc = (lane < 16 && (lane & 3) == 0) ? dbin : 0.0f;
#pragma unroll
        for (int o = 16; o > 0; o >>= 1) dc += __shfl_xor_sync(~0u, dc, o);

        ace   += lse - slab;
        aciou += 1.0f - ciou;
        aiou  += iou;
        apos  += prob_o * sigmoidf(slab);
        adfl  += dc;
    }

    // ---- block reduction: light (warp sums) + heavy (warp-uniform) ----
#pragma unroll
    for (int o = 16; o > 0; o >>= 1) {
        l_focal += __shfl_xor_sync(~0u, l_focal, o);
        l_cnt   += __shfl_xor_sync(~0u, l_cnt, o);
        l_neg   += __shfl_xor_sync(~0u, l_neg, o);
    }
    if (lane == 0) {
        wred[w][0] = l_focal; wred[w][1] = l_cnt; wred[w][2] = aciou;
        wred[w][3] = aiou;    wred[w][4] = ace;   wred[w][5] = adfl;
        wred[w][6] = apos;    wred[w][7] = l_neg;
    }
    __syncthreads();
    if (t < 8) {
        float s = 0.0f;
#pragma unroll
        for (int ww = 0; ww < 8; ww++) s += wred[ww][t];
        g_partial[b][blockIdx.x][t] = s;
    }

    // ---- global last block: final scalars ----
    __threadfence();
    __syncthreads();
    if (t == 0) is_last = (atomicAdd(&g_ctr_loss, 1) == CHUNKS * BATCH - 1);
    __syncthreads();
    if (!is_last) return;
    if (t == 0) g_ctr_loss = 0;
    __threadfence();

    if (t < BATCH * 8) {
        int b2 = t >> 3, q = t & 7;
        float s = 0.0f;
#pragma unroll
        for (int c = 0; c < CHUNKS; c++) s += g_partial[b2][c][q];
        img[b2][q] = s;
    }
    __syncthreads();
    if (t == 0) {
        float tot_obj = 0, tot_iou = 0, tot_match = 0, tot_dfl = 0;
        float tot_pos = 0, miou = 0, pos = 0, neg = 0;
        for (int b2 = 0; b2 < BATCH; b2++) {
            float cnt = img[b2][1];
            float cs = fmaxf(cnt, 1.0f);
            tot_obj   += img[b2][0] / (float)NA;
            tot_iou   += img[b2][2] / cs;
            tot_match += img[b2][4] / cs;
            tot_dfl   += img[b2][5] / (4.0f * cs);
            tot_pos   += cnt;
            miou += img[b2][3];
            pos  += img[b2][6];
            neg  += img[b2][7];
        }
        float tot_neg = (float)(BATCH * NA) - tot_pos;
        float nb = (float)BATCH;
        float loss = (tot_obj + tot_match + 7.5f * tot_iou + 1.5f * tot_dfl) / nb;
        out[0] = loss;
        out[1] = tot_obj / nb;
        out[2] = tot_match / nb;
        out[3] = tot_iou / nb;
        out[4] = tot_dfl / nb;
        out[5] = tot_pos;
        out[6] = tot_neg;
        out[7] = pos / fmaxf(tot_pos, 1.0f);
        out[8] = neg / fmaxf(tot_neg, 1.0f);
        out[9] = miou / fmaxf(tot_pos, 1.0f);
    }
}

// ---------------- launch ----------------
extern "C" void kernel_launch(void* const* d_in, const int* in_sizes, int n_in,
                              void* d_out, int out_size) {
    const float* pred_boxes    = (const float*)d_in[0];
    const float* pred_scores   = (const float*)d_in[1];
    const float* pred_obj      = (const float*)d_in[2];
    const float* anchor_points = (const float*)d_in[3];
    const float* stride_tensor = (const float*)d_in[4];
    const float* box_dist      = (const float*)d_in[5];
    const void*  class_mask    = d_in[6];
    const float* gt_boxes      = (const float*)d_in[7];
    const void*  gt_labels     = d_in[8];
    float* out = (float*)d_out;

    dim3 g(CHUNKS, BATCH);
    k_prep<<<1, 256>>>(class_mask, gt_labels);
    k_main<<<g, 256>>>(pred_boxes, pred_scores, anchor_points, gt_boxes);
    k_loss<<<g, 256>>>(pred_boxes, pred_scores, pred_obj, anchor_points,
                       stride_tensor, box_dist, gt_boxes, out);
}

// round 9
// speedup vs baseline: 1.0017x; 1.0017x over previous
#include <cuda_runtime.h>
#include <cstdint>

#define BATCH 16
#define NA    8400
#define NC    80
#define NM    24
#define KTOP  13
#define REG   16
#define CH    256
#define CHUNKS 33   // ceil(8400/256)

// ---------------- device scratch ----------------
__device__ unsigned long long g_best[BATCH * NA];
__device__ unsigned long long g_cand[BATCH * NM * CHUNKS * KTOP];
__device__ float g_mx[BATCH * NA];
__device__ float g_cmask[BATCH * NC];
__device__ int   g_lab[BATCH * NM];
__device__ int   g_val[BATCH * NM];
__device__ float g_partial[BATCH][CHUNKS][8];
__device__ int   g_ctr_main[BATCH];           // zero-init; self-resetting
__device__ int   g_ctr_loss;                  // zero-init; self-resetting

// ---------------- helpers ----------------
__device__ __forceinline__ float sigmoidf(float x) { return 1.0f / (1.0f + expf(-x)); }

__device__ __forceinline__ float iou_box(float a0, float a1, float a2, float a3,
                                         float b0, float b1, float b2, float b3) {
    float lt0 = fmaxf(a0, b0), lt1 = fmaxf(a1, b1);
    float rb0 = fminf(a2, b2), rb1 = fminf(a3, b3);
    float w = fmaxf(rb0 - lt0, 0.0f), h = fmaxf(rb1 - lt1, 0.0f);
    float inter = w * h;
    float aa = fmaxf(a2 - a0, 0.0f) * fmaxf(a3 - a1, 0.0f);
    float ab = fmaxf(b2 - b0, 0.0f) * fmaxf(b3 - b1, 0.0f);
    return inter / (aa + ab - inter + 1e-7f);
}

__device__ __forceinline__ float load_cmask_raw(const void* cm, int cmode, int i) {
    float v;
    if (cmode == 0)      v = ((const float*)cm)[i];
    else if (cmode == 1) v = (float)(((const int*)cm)[i] != 0);
    else                 v = (float)(((const unsigned char*)cm)[i] != 0);
    return (v != 0.0f) ? 1.0f : 0.0f;
}

// ============ k_prep: one block, parallel dtype detect + normalize ============
__global__ __launch_bounds__(256) void k_prep(const void* __restrict__ cm,
                                              const void* __restrict__ lab) {
    __shared__ int flag_c, flag_l;
    int t = threadIdx.x;
    if (t == 0) { flag_c = 0; flag_l = 0; }
    __syncthreads();

    const unsigned* cw = (const unsigned*)cm;
    if (t < 80 && cw[t] > 1u) atomicOr(&flag_c, 1);
    const unsigned* lw = (const unsigned*)lab;
    for (int i = t; i < BATCH * NM; i += 256)
        if (lw[i] > 1000u) atomicOr(&flag_l, 1);
    __syncthreads();

    int cmode = (cw[0] == 0x3F800000u) ? 0 : (flag_c ? 2 : 1);
    int lmode = flag_l;

    for (int i = t; i < BATCH * NC; i += 256)
        g_cmask[i] = load_cmask_raw(cm, cmode, i);
    for (int i = t; i < BATCH * NM; i += 256) {
        int lb = lmode ? (int)(((const float*)lab)[i]) : ((const int*)lab)[i];
        int labc = min(max(lb, 0), NC - 1);
        int b = i / NM;
        g_lab[i] = labc;
        g_val[i] = (lb >= 0 && lb < NC) &&
                   (load_cmask_raw(cm, cmode, b * NC + labc) != 0.0f);
    }
}

// ============ k_main: masked max + align + local top-13 + (last block) merge/scatter ============
__global__ __launch_bounds__(256) void k_main(const float* __restrict__ pb,
                                              const float* __restrict__ ps,
                                              const float* __restrict__ ap,
                                              const float* __restrict__ gtb) {
    __shared__ float4 cm4_s[20];
    __shared__ int   lab_s[NM];
    __shared__ int   val_s[NM];
    __shared__ float4 gtb_s[NM];
    __shared__ float pm[8][32][21];
    __shared__ float align_s[NM][CH + 1];
    __shared__ int   is_last;

    int chunk = blockIdx.x, b = blockIdx.y, t = threadIdx.x;
    int lane = t & 31, w = t >> 5;
    int nbase = chunk * CH;

    if (t < 20) cm4_s[t] = ((const float4*)(g_cmask + b * NC))[t];
    if (t < NM) {
        lab_s[t] = g_lab[b * NM + t];
        val_s[t] = g_val[b * NM + t];
        gtb_s[t] = ((const float4*)gtb)[b * NM + t];
    }
#pragma unroll 4
    for (int g = 0; g < NM; g++) align_s[g][t] = -1.0f;
    if (nbase + t < NA) g_best[b * NA + nbase + t] = 0ull;
    __syncthreads();

    int a0 = nbase + w * 32;
    int alim = min(32, NA - a0);          // warp-uniform

    // Phase A: coalesced score read, lane-partial masked max -> smem.
    // Full-warp case fully unrolled: 32 independent LDG.128s in flight.
    if (lane < 20 && alim > 0) {
        const float4* row4 = (const float4*)(ps + ((size_t)b * NA + a0) * NC);
        float4 m4 = cm4_s[lane];
        if (alim == 32) {
#pragma unroll
            for (int a = 0; a < 32; a++) {
                float4 s4 = row4[(size_t)a * 20 + lane];
                float m = -1e30f;
                m = fmaxf(m, m4.x != 0.0f ? s4.x : -1e30f);
                m = fmaxf(m, m4.y != 0.0f ? s4.y : -1e30f);
                m = fmaxf(m, m4.z != 0.0f ? s4.z : -1e30f);
                m = fmaxf(m, m4.w != 0.0f ? s4.w : -1e30f);
                pm[w][a][lane] = m;
            }
        } else {
            for (int a = 0; a < alim; a++) {
                float4 s4 = row4[(size_t)a * 20 + lane];
                float m = -1e30f;
                m = fmaxf(m, m4.x != 0.0f ? s4.x : -1e30f);
                m = fmaxf(m, m4.y != 0.0f ? s4.y : -1e30f);
                m = fmaxf(m, m4.z != 0.0f ? s4.z : -1e30f);
                m = fmaxf(m, m4.w != 0.0f ? s4.w : -1e30f);
                pm[w][a][lane] = m;
            }
        }
    }
    __syncwarp();

    // Phase B: per-lane reduce own anchor's 20 partials, coalesced store
    if (lane < alim) {
        float m = -1e30f;
#pragma unroll
        for (int j = 0; j < 20; j++) m = fmaxf(m, pm[w][lane][j]);
        g_mx[b * NA + a0 + lane] = m;
    }

    // Phase C: align; lane owns anchor, loop GTs
    int n = a0 + lane;
    if (n < NA && alim > 0) {
        float2 apc = ((const float2*)ap)[n];
        float4 pbx = ((const float4*)pb)[(size_t)b * NA + n];
        const float* srow = ps + ((size_t)b * NA + n) * NC;
#pragma unroll 4
        for (int g = 0; g < NM; g++) {
            float4 gbx = gtb_s[g];
            bool inside = val_s[g] && apc.x >= gbx.x && apc.x <= gbx.z &&
                          apc.y >= gbx.y && apc.y <= gbx.w;
            if (inside) {
                float iou = iou_box(pbx.x, pbx.y, pbx.z, pbx.w, gbx.x, gbx.y, gbx.z, gbx.w);
                float cls = sigmoidf(srow[lab_s[g]]);
                float i2 = iou * iou;
                align_s[g][w * 32 + lane] = cls * (i2 * i2 * i2);
            }
        }
    }
    __syncthreads();

    // Phase D: local top-13; warp w handles GTs w, w+8, w+16
#pragma unroll
    for (int gi = 0; gi < 3; gi++) {
        int g = w + gi * 8;
        unsigned long long key[8];
        unsigned ball[8];
        int base[8], tot = 0;
#pragma unroll
        for (int r = 0; r < 8; r++) {
            float v = align_s[g][lane + 32 * r];
            int nn = nbase + lane + 32 * r;
            key[r] = (v >= 0.0f)
                ? (((unsigned long long)__float_as_uint(v) << 32) | (unsigned)(0xFFFFFFFFu - nn))
                : 0ull;
            ball[r] = __ballot_sync(~0u, key[r] != 0ull);
            base[r] = tot;
            tot += __popc(ball[r]);
        }
        unsigned long long* outc = g_cand + (((size_t)b * NM + g) * CHUNKS + chunk) * KTOP;

        if (tot <= KTOP) {
            unsigned lt = (1u << lane) - 1u;
#pragma unroll
            for (int r = 0; r < 8; r++) {
                if (key[r] != 0ull) {
                    int slot = base[r] + __popc(ball[r] & lt);
                    outc[slot] = key[r];
                }
            }
            if (lane >= tot && lane < KTOP) outc[lane] = 0ull;
        } else {
            for (int k = 0; k < KTOP; k++) {
                unsigned long long lm = key[0]; int lr = 0;
#pragma unroll
                for (int r = 1; r < 8; r++) if (key[r] > lm) { lm = key[r]; lr = r; }
                unsigned long long wm = lm;
#pragma unroll
                for (int o = 16; o > 0; o >>= 1) {
                    unsigned long long oth = __shfl_xor_sync(~0u, wm, o);
                    if (oth > wm) wm = oth;
                }
                if (lm == wm) key[lr] = 0ull;
                if (lane == 0) outc[k] = wm;
            }
        }
    }

    // ---- last block of this batch: merge + scatter ----
    __threadfence();
    __syncthreads();
    if (t == 0) is_last = (atomicAdd(&g_ctr_main[b], 1) == CHUNKS - 1);
    __syncthreads();
    if (!is_last) return;
    if (t == 0) g_ctr_main[b] = 0;
    __threadfence();

#pragma unroll
    for (int gi = 0; gi < 3; gi++) {
        int g = w + gi * 8;
        const unsigned long long* src = g_cand + ((size_t)b * NM + g) * CHUNKS * KTOP;
        unsigned long long key[14];
#pragma unroll
        for (int r = 0; r < 14; r++) {
            int e = lane + 32 * r;
            key[r] = (e < CHUNKS * KTOP) ? src[e] : 0ull;
        }
        unsigned pri = (unsigned)(NM - g);
        for (int k = 0; k < KTOP; k++) {
            unsigned long long lm = key[0]; int lr = 0;
#pragma unroll
            for (int r = 1; r < 14; r++) if (key[r] > lm) { lm = key[r]; lr = r; }
            unsigned long long wm = lm;
#pragma unroll
            for (int o = 16; o > 0; o >>= 1) {
                unsigned long long oth = __shfl_xor_sync(~0u, wm, o);
                if (oth > wm) wm = oth;
            }
            if (wm == 0ull) break;
            if (lm == wm) {
                key[lr] = 0ull;
                int nn = (int)(0xFFFFFFFFu - (unsigned)(wm & 0xFFFFFFFFull));
                unsigned long long key2 = (wm & 0xFFFFFFFF00000000ull) | pri;
                atomicMax(&g_best[b * NA + nn], key2);
            }
        }
    }
}

// ============ k_loss: light terms + deterministic fg compaction + warp-coop heavy + final ============
__global__ __launch_bounds__(256) void k_loss(const float* __restrict__ pb,
                                              const float* __restrict__ ps,
                                              const float* __restrict__ pobj,
                                              const float* __restrict__ ap,
                                              const float* __restrict__ st,
                                              const float* __restrict__ bd,
                                              const float* __restrict__ gtb,
                                              float* __restrict__ out) {
    __shared__ float4 cm4_s[20];
    __shared__ float wred[8][8];
    __shared__ int   scnt[8];
    __shared__ int   sbase[9];
    __shared__ int   slist[CH];     // (n_local << 5) | g
    __shared__ int   is_last;
    __shared__ float img[BATCH][8];

    int b = blockIdx.y, t = threadIdx.x;
    int lane = t & 31, w = t >> 5;
    int nb0 = blockIdx.x * CH;
    int n = nb0 + t;

    if (t < 20) cm4_s[t] = ((const float4*)(g_cmask + b * NC))[t];

    // ---- light terms + fg detection ----
    float l_focal = 0.0f, l_cnt = 0.0f, l_neg = 0.0f;
    int my_g = 0;
    bool fg = false;
    if (n < NA) {
        unsigned long long key = g_best[b * NA + n];
        fg = (key != 0ull);
        float x = pobj[(size_t)b * NA + n];
        float tt = fg ? 1.0f : 0.0f;
        float ce_o = fmaxf(x, 0.0f) - x * tt + log1pf(expf(-fabsf(x)));
        float prob_o = sigmoidf(x);
        float p_t = fg ? prob_o : (1.0f - prob_o);
        float af  = fg ? 0.25f  : 0.75f;
        float om  = 1.0f - p_t;
        l_focal = ce_o * af * om * om;
        if (fg) { l_cnt = 1.0f; my_g = NM - (int)(key & 0xFFFFFFFFull); }
        else    l_neg = prob_o * sigmoidf(g_mx[b * NA + n]);
    }

    // deterministic compaction: per-warp ballot, warp-ordered bases
    unsigned ball = __ballot_sync(~0u, fg);
    if (lane == 0) scnt[w] = __popc(ball);
    __syncthreads();
    if (t == 0) {
        sbase[0] = 0;
#pragma unroll
        for (int ww = 0; ww < 8; ww++) sbase[ww + 1] = sbase[ww] + scnt[ww];
    }
    __syncthreads();
    int tot = sbase[8];
    if (fg) {
        int slot = sbase[w] + __popc(ball & ((1u << lane) - 1u));
        slist[slot] = (t << 5) | my_g;
    }
    __syncthreads();

    // ---- heavy terms: warp-cooperative, warps round-robin the fg list ----
    float ace = 0, aciou = 0, aiou = 0, apos = 0, adfl = 0;
    float4 m4 = (lane < 20) ? cm4_s[lane] : make_float4(0, 0, 0, 0);

    for (int i = w; i < tot; i += 8) {
        int e = slist[i];
        int nn = nb0 + (e >> 5);
        int g = e & 31;
        size_t off = (size_t)b * NA + nn;
        int lab = g_lab[b * NM + g];
        float4 gb4 = ((const float4*)gtb)[b * NM + g];
        float mx = g_mx[off];

        // masked LSE over 80 classes, 20 lanes, coalesced float4
        float4 s4 = (lane < 20) ? ((const float4*)(ps + off * NC))[lane]
                                : make_float4(0, 0, 0, 0);
        float es = 0.0f;
        es += (m4.x != 0.0f) ? expf(s4.x - mx) : 0.0f;
        es += (m4.y != 0.0f) ? expf(s4.y - mx) : 0.0f;
        es += (m4.z != 0.0f) ? expf(s4.z - mx) : 0.0f;
        es += (m4.w != 0.0f) ? expf(s4.w - mx) : 0.0f;
#pragma unroll
        for (int o = 16; o > 0; o >>= 1) es += __shfl_xor_sync(~0u, es, o);
        float lse = mx + logf(es);

        int sl = lab >> 2, sc = lab & 3;
        float c0 = __shfl_sync(~0u, s4.x, sl);
        float c1 = __shfl_sync(~0u, s4.y, sl);
        float c2v = __shfl_sync(~0u, s4.z, sl);
        float c3 = __shfl_sync(~0u, s4.w, sl);
        float slab = (sc == 0) ? c0 : (sc == 1) ? c1 : (sc == 2) ? c2v : c3;

        float prob_o = sigmoidf(pobj[off]);

        // IoU / CIoU (redundant across lanes, warp-uniform)
        float4 a4 = ((const float4*)pb)[off];
        float iou = iou_box(a4.x, a4.y, a4.z, a4.w, gb4.x, gb4.y, gb4.z, gb4.w);
        float cw = fmaxf(a4.z, gb4.z) - fminf(a4.x, gb4.x);
        float ch = fmaxf(a4.w, gb4.w) - fminf(a4.y, gb4.y);
        float c2 = cw * cw + ch * ch + 1e-7f;
        float dx = a4.x + a4.z - gb4.x - gb4.z;
        float dy = a4.y + a4.w - gb4.y - gb4.w;
        float rho2 = (dx * dx + dy * dy) * 0.25f;
        float w1 = a4.z - a4.x, h1 = a4.w - a4.y;
        float w2 = gb4.z - gb4.x, h2 = gb4.w - gb4.y;
        float dat = atanf(w2 / (h2 + 1e-7f)) - atanf(w1 / (h1 + 1e-7f));
        float v = (4.0f / (3.14159265358979323846f * 3.14159265358979323846f)) * dat * dat;
        float alpha = v / (v - iou + 1.0f + 1e-7f);
        float ciou = iou - rho2 / c2 - v * alpha;

        // DFL: 16 lanes hold 64 logits, 4-lane groups per bin
        float4 d4 = (lane < 16) ? ((const float4*)(bd + off * (4 * REG)))[lane]
                                : make_float4(0, 0, 0, 0);
        int j = (lane >> 2) & 3;
        float2 apc = ((const float2*)ap)[nn];
        float s = st[nn];
        float tj = (j == 0) ? (apc.x - gb4.x) / s :
                   (j == 1) ? (apc.y - gb4.y) / s :
                   (j == 2) ? (gb4.z - apc.x) / s :
                              (gb4.w - apc.y) / s;
        float tv = fminf(fmaxf(tj, 0.0f), (float)(REG - 1) - 0.01f);
        int tl = (int)tv;
        int tr = min(tl + 1, REG - 1);
        float wl = (float)tr - tv;
        float wr = 1.0f - wl;

        float lmax = fmaxf(fmaxf(d4.x, d4.y), fmaxf(d4.z, d4.w));
        lmax = fmaxf(lmax, __shfl_xor_sync(~0u, lmax, 1));
        lmax = fmaxf(lmax, __shfl_xor_sync(~0u, lmax, 2));
        float lsum = expf(d4.x - lmax) + expf(d4.y - lmax) +
                     expf(d4.z - lmax) + expf(d4.w - lmax);
        lsum += __shfl_xor_sync(~0u, lsum, 1);
        lsum += __shfl_xor_sync(~0u, lsum, 2);
        float lse2 = lmax + logf(lsum);

        int baseL = lane & ~3;
        int stl = baseL + (tl >> 2), str_ = baseL + (tr >> 2);
        float tlx = __shfl_sync(~0u, d4.x, stl), tly = __shfl_sync(~0u, d4.y, stl);
        float tlz = __shfl_sync(~0u, d4.z, stl), tlw = __shfl_sync(~0u, d4.w, stl);
        int cl = tl & 3;
        float vtl = (cl == 0) ? tlx : (cl == 1) ? tly : (cl == 2) ? tlz : tlw;
        float trx = __shfl_sync(~0u, d4.x, str_), try_ = __shfl_sync(~0u, d4.y, str_);
        float trz = __shfl_sync(~0u, d4.z, str_), trw = __shfl_sync(~0u, d4.w, str_);
        int cr = tr & 3;
        float vtr = (cr == 0) ? trx : (cr == 1) ? try_ : (cr == 2) ? trz : trw;
        float dbin = (lse2 - vtl) * wl + (lse2 - vtr) * wr;
        float dc = (lane < 16 && (lane & 3) == 0) ? dbin : 0.0f;
#pragma unroll
        for (int o = 16; o > 0; o >>= 1) dc += __shfl_xor_sync(~0u, dc, o);

        ace   += lse - slab;
        aciou += 1.0f - ciou;
        aiou  += iou;
        apos  += prob_o * sigmoidf(slab);
        adfl  += dc;
    }

    // ---- block reduction: light (warp sums) + heavy (warp-uniform) ----
#pragma unroll
    for (int o = 16; o > 0; o >>= 1) {
        l_focal += __shfl_xor_sync(~0u, l_focal, o);
        l_cnt   += __shfl_xor_sync(~0u, l_cnt, o);
        l_neg   += __shfl_xor_sync(~0u, l_neg, o);
    }
    if (lane == 0) {
        wred[w][0] = l_focal; wred[w][1] = l_cnt; wred[w][2] = aciou;
        wred[w][3] = aiou;    wred[w][4] = ace;   wred[w][5] = adfl;
        wred[w][6] = apos;    wred[w][7] = l_neg;
    }
    __syncthreads();
    if (t < 8) {
        float s = 0.0f;
#pragma unroll
        for (int ww = 0; ww < 8; ww++) s += wred[ww][t];
        g_partial[b][blockIdx.x][t] = s;
    }

    // ---- global last block: final scalars ----
    __threadfence();
    __syncthreads();
    if (t == 0) is_last = (atomicAdd(&g_ctr_loss, 1) == CHUNKS * BATCH - 1);
    __syncthreads();
    if (!is_last) return;
    if (t == 0) g_ctr_loss = 0;
    __threadfence();

    if (t < BATCH * 8) {
        int b2 = t >> 3, q = t & 7;
        float s = 0.0f;
#pragma unroll
        for (int c = 0; c < CHUNKS; c++) s += g_partial[b2][c][q];
        img[b2][q] = s;
    }
    __syncthreads();
    if (t == 0) {
        float tot_obj = 0, tot_iou = 0, tot_match = 0, tot_dfl = 0;
        float tot_pos = 0, miou = 0, pos = 0, neg = 0;
        for (int b2 = 0; b2 < BATCH; b2++) {
            float cnt = img[b2][1];
            float cs = fmaxf(cnt, 1.0f);
            tot_obj   += img[b2][0] / (float)NA;
            tot_iou   += img[b2][2] / cs;
            tot_match += img[b2][4] / cs;
            tot_dfl   += img[b2][5] / (4.0f * cs);
            tot_pos   += cnt;
            miou += img[b2][3];
            pos  += img[b2][6];
            neg  += img[b2][7];
        }
        float tot_neg = (float)(BATCH * NA) - tot_pos;
        float nb = (float)BATCH;
        float loss = (tot_obj + tot_match + 7.5f * tot_iou + 1.5f * tot_dfl) / nb;
        out[0] = loss;
        out[1] = tot_obj / nb;
        out[2] = tot_match / nb;
        out[3] = tot_iou / nb;
        out[4] = tot_dfl / nb;
        out[5] = tot_pos;
        out[6] = tot_neg;
        out[7] = pos / fmaxf(tot_pos, 1.0f);
        out[8] = neg / fmaxf(tot_neg, 1.0f);
        out[9] = miou / fmaxf(tot_pos, 1.0f);
    }
}

// ---------------- launch ----------------
extern "C" void kernel_launch(void* const* d_in, const int* in_sizes, int n_in,
                              void* d_out, int out_size) {
    const float* pred_boxes    = (const float*)d_in[0];
    const float* pred_scores   = (const float*)d_in[1];
    const float* pred_obj      = (const float*)d_in[2];
    const float* anchor_points = (const float*)d_in[3];
    const float* stride_tensor = (const float*)d_in[4];
    const float* box_dist      = (const float*)d_in[5];
    const void*  class_mask    = d_in[6];
    const float* gt_boxes      = (const float*)d_in[7];
    const void*  gt_labels     = d_in[8];
    float* out = (float*)d_out;

    dim3 g(CHUNKS, BATCH);
    k_prep<<<1, 256>>>(class_mask, gt_labels);
    k_main<<<g, 256>>>(pred_boxes, pred_scores, anchor_points, gt_boxes);
    k_loss<<<g, 256>>>(pred_boxes, pred_scores, pred_obj, anchor_points,
                       stride_tensor, box_dist, gt_boxes, out);
}

// round 10
// speedup vs baseline: 1.0544x; 1.0526x over previous
#include <cuda_runtime.h>
#include <cstdint>

#define BATCH 16
#define NA    8400
#define NC    80
#define NM    24
#define KTOP  13
#define REG   16
#define CH    256
#define CHUNKS 33   // ceil(8400/256)

// ---------------- device scratch ----------------
__device__ unsigned long long g_best[BATCH * NA];
__device__ unsigned long long g_cand[BATCH * NM * CHUNKS * KTOP];
__device__ float g_partial[BATCH][CHUNKS][8];
__device__ int   g_ctr_main[BATCH];   // zero-init; self-resetting
__device__ int   g_ctr_loss;          // zero-init; self-resetting
__device__ int   g_flag[BATCH];       // zero-init; self-resetting

// ---------------- helpers ----------------
__device__ __forceinline__ float sigmoidf(float x) { return 1.0f / (1.0f + expf(-x)); }

__device__ __forceinline__ float iou_box(float a0, float a1, float a2, float a3,
                                         float b0, float b1, float b2, float b3) {
    float lt0 = fmaxf(a0, b0), lt1 = fmaxf(a1, b1);
    float rb0 = fminf(a2, b2), rb1 = fminf(a3, b3);
    float w = fmaxf(rb0 - lt0, 0.0f), h = fmaxf(rb1 - lt1, 0.0f);
    float inter = w * h;
    float aa = fmaxf(a2 - a0, 0.0f) * fmaxf(a3 - a1, 0.0f);
    float ab = fmaxf(b2 - b0, 0.0f) * fmaxf(b3 - b1, 0.0f);
    return inter / (aa + ab - inter + 1e-7f);
}

struct LossSmem {
    int   slist[CH];
    float wred[8][8];
    int   scnt[8];
    int   sbase[9];
    float img[BATCH][8];
};

// ============ k_all: the whole loss in ONE kernel ============
__global__ __launch_bounds__(256, 4) void k_all(const float* __restrict__ pb,
                                                const float* __restrict__ ps,
                                                const float* __restrict__ pobj,
                                                const float* __restrict__ ap,
                                                const float* __restrict__ st,
                                                const float* __restrict__ bd,
                                                const float* __restrict__ gtb,
                                                const void* __restrict__ cm_raw,
                                                const void* __restrict__ lab_raw,
                                                float* __restrict__ out) {
    __shared__ float  cm_s[NC];
    __shared__ float4 cm4_s[20];
    __shared__ int    lab_s[NM];
    __shared__ int    val_s[NM];
    __shared__ float4 gtb_s[NM];
    __shared__ float  pm[8][32][21];   // [..][..][0:20)=lane partial max, [20]=anchor mx
    __shared__ union SmemU { float align[NM][CH]; LossSmem l; } u;
    __shared__ int    detf[2];
    __shared__ int    is_last;

    int chunk = blockIdx.x, b = blockIdx.y, t = threadIdx.x;
    int lane = t & 31, w = t >> 5;
    int nbase = chunk * CH;

    // ---- per-block parallel dtype detect (reads ~320 broadcast bytes) ----
    if (t == 0) { detf[0] = 0; detf[1] = 0; }
    __syncthreads();
    const unsigned* cw = (const unsigned*)cm_raw;
    if (t < 80 && cw[t] > 1u) atomicOr(&detf[0], 1);
    if (t < NM && ((const unsigned*)lab_raw)[b * NM + t] > 1000u) atomicOr(&detf[1], 1);
#pragma unroll 4
    for (int g = 0; g < NM; g++) u.align[g][t] = -1.0f;
    if (nbase + t < NA) g_best[b * NA + nbase + t] = 0ull;
    __syncthreads();
    int cmode = (cw[0] == 0x3F800000u) ? 0 : (detf[0] ? 2 : 1);
    int lmode = detf[1];

    if (t < NC) {
        float v;
        int i = b * NC + t;
        if (cmode == 0)      v = ((const float*)cm_raw)[i];
        else if (cmode == 1) v = (float)(((const int*)cm_raw)[i] != 0);
        else                 v = (float)(((const unsigned char*)cm_raw)[i] != 0);
        cm_s[t] = (v != 0.0f) ? 1.0f : 0.0f;
    }
    if (t < NM) {
        int lb = lmode ? (int)(((const float*)lab_raw)[b * NM + t])
                       : ((const int*)lab_raw)[b * NM + t];
        int labc = min(max(lb, 0), NC - 1);
        lab_s[t] = labc;
        val_s[t] = (lb >= 0 && lb < NC);
        gtb_s[t] = ((const float4*)gtb)[b * NM + t];
    }
    __syncthreads();
    if (t < NM) val_s[t] = val_s[t] && (cm_s[lab_s[t]] != 0.0f);
    if (t < 20) cm4_s[t] = ((const float4*)cm_s)[t];
    __syncthreads();

    int a0 = nbase + w * 32;
    int alim = min(32, NA - a0);          // warp-uniform

    // ---- Phase A: coalesced score read, lane-partial masked max -> smem ----
    if (lane < 20 && alim > 0) {
        const float4* row4 = (const float4*)(ps + ((size_t)b * NA + a0) * NC);
        float4 m4 = cm4_s[lane];
        if (alim == 32) {
#pragma unroll
            for (int a = 0; a < 32; a++) {
                float4 s4 = row4[(size_t)a * 20 + lane];
                float m = -1e30f;
                m = fmaxf(m, m4.x != 0.0f ? s4.x : -1e30f);
                m = fmaxf(m, m4.y != 0.0f ? s4.y : -1e30f);
                m = fmaxf(m, m4.z != 0.0f ? s4.z : -1e30f);
                m = fmaxf(m, m4.w != 0.0f ? s4.w : -1e30f);
                pm[w][a][lane] = m;
            }
        } else {
            for (int a = 0; a < alim; a++) {
                float4 s4 = row4[(size_t)a * 20 + lane];
                float m = -1e30f;
                m = fmaxf(m, m4.x != 0.0f ? s4.x : -1e30f);
                m = fmaxf(m, m4.y != 0.0f ? s4.y : -1e30f);
                m = fmaxf(m, m4.z != 0.0f ? s4.z : -1e30f);
                m = fmaxf(m, m4.w != 0.0f ? s4.w : -1e30f);
                pm[w][a][lane] = m;
            }
        }
    }
    __syncwarp();

    // ---- Phase B: per-lane reduce own anchor's 20 partials -> pm[w][a][20] ----
    if (lane < alim) {
        float m = -1e30f;
#pragma unroll
        for (int j = 0; j < 20; j++) m = fmaxf(m, pm[w][lane][j]);
        pm[w][lane][20] = m;
    }
    __syncwarp();

    // ---- Phase C: align; lane owns anchor, loop GTs ----
    int n = a0 + lane;
    if (n < NA && alim > 0) {
        float2 apc = ((const float2*)ap)[n];
        float4 pbx = ((const float4*)pb)[(size_t)b * NA + n];
        const float* srow = ps + ((size_t)b * NA + n) * NC;
#pragma unroll 4
        for (int g = 0; g < NM; g++) {
            float4 gbx = gtb_s[g];
            bool inside = val_s[g] && apc.x >= gbx.x && apc.x <= gbx.z &&
                          apc.y >= gbx.y && apc.y <= gbx.w;
            if (inside) {
                float iou = iou_box(pbx.x, pbx.y, pbx.z, pbx.w, gbx.x, gbx.y, gbx.z, gbx.w);
                float cls = sigmoidf(srow[lab_s[g]]);
                float i2 = iou * iou;
                u.align[g][w * 32 + lane] = cls * (i2 * i2 * i2);
            }
        }
    }
    __syncthreads();

    // ---- Phase D: local top-13; warp w handles GTs w, w+8, w+16 ----
#pragma unroll
    for (int gi = 0; gi < 3; gi++) {
        int g = w + gi * 8;
        unsigned long long key[8];
        unsigned ball[8];
        int base[8], tot = 0;
#pragma unroll
        for (int r = 0; r < 8; r++) {
            float v = u.align[g][lane + 32 * r];
            int nn = nbase + lane + 32 * r;
            key[r] = (v >= 0.0f)
                ? (((unsigned long long)__float_as_uint(v) << 32) | (unsigned)(0xFFFFFFFFu - nn))
                : 0ull;
            ball[r] = __ballot_sync(~0u, key[r] != 0ull);
            base[r] = tot;
            tot += __popc(ball[r]);
        }
        unsigned long long* outc = g_cand + (((size_t)b * NM + g) * CHUNKS + chunk) * KTOP;

        if (tot <= KTOP) {
            unsigned lt = (1u << lane) - 1u;
#pragma unroll
            for (int r = 0; r < 8; r++) {
                if (key[r] != 0ull) {
                    int slot = base[r] + __popc(ball[r] & lt);
                    outc[slot] = key[r];
                }
            }
            if (lane >= tot && lane < KTOP) outc[lane] = 0ull;
        } else {
            for (int k = 0; k < KTOP; k++) {
                unsigned long long lm = key[0]; int lr = 0;
#pragma unroll
                for (int r = 1; r < 8; r++) if (key[r] > lm) { lm = key[r]; lr = r; }
                unsigned long long wm = lm;
#pragma unroll
                for (int o = 16; o > 0; o >>= 1) {
                    unsigned long long oth = __shfl_xor_sync(~0u, wm, o);
                    if (oth > wm) wm = oth;
                }
                if (lm == wm) key[lr] = 0ull;
                if (lane == 0) outc[k] = wm;
            }
        }
    }

    // ---- per-batch arrival; last block merges + scatters + releases flag ----
    __threadfence();
    __syncthreads();
    if (t == 0) is_last = (atomicAdd(&g_ctr_main[b], 1) == CHUNKS - 1);
    __syncthreads();
    if (is_last) {
        if (t == 0) g_ctr_main[b] = 0;   // reset for next replay
        __threadfence();                 // acquire all blocks' g_cand writes
#pragma unroll
        for (int gi = 0; gi < 3; gi++) {
            int g = w + gi * 8;
            const unsigned long long* src = g_cand + ((size_t)b * NM + g) * CHUNKS * KTOP;
            unsigned long long key[14];
#pragma unroll
            for (int r = 0; r < 14; r++) {
                int e = lane + 32 * r;
                key[r] = (e < CHUNKS * KTOP) ? src[e] : 0ull;
            }
            unsigned pri = (unsigned)(NM - g);
            for (int k = 0; k < KTOP; k++) {
                unsigned long long lm = key[0]; int lr = 0;
#pragma unroll
                for (int r = 1; r < 14; r++) if (key[r] > lm) { lm = key[r]; lr = r; }
                unsigned long long wm = lm;
#pragma unroll
                for (int o = 16; o > 0; o >>= 1) {
                    unsigned long long oth = __shfl_xor_sync(~0u, wm, o);
                    if (oth > wm) wm = oth;
                }
                if (wm == 0ull) break;
                if (lm == wm) {
                    key[lr] = 0ull;
                    int nn = (int)(0xFFFFFFFFu - (unsigned)(wm & 0xFFFFFFFFull));
                    unsigned long long key2 = (wm & 0xFFFFFFFF00000000ull) | pri;
                    atomicMax(&g_best[b * NA + nn], key2);
                }
            }
        }
        __threadfence();
        __syncthreads();
        if (t == 0) atomicExch(&g_flag[b], 1);
    }

    // ---- wait for this batch's merge (all 528 blocks co-resident: single wave) ----
    if (t == 0) {
        while (atomicAdd(&g_flag[b], 0) == 0) __nanosleep(64);
    }
    __syncthreads();
    __threadfence();

    // ================= loss phase (same block, same chunk) =================
    float l_focal = 0.0f, l_cnt = 0.0f, l_neg = 0.0f;
    int my_g = 0;
    bool fg = false;
    if (n < NA) {   // n = a0 + lane = nbase + t
        unsigned long long key = g_best[b * NA + n];
        fg = (key != 0ull);
        float x = pobj[(size_t)b * NA + n];
        float tt = fg ? 1.0f : 0.0f;
        float ce_o = fmaxf(x, 0.0f) - x * tt + log1pf(expf(-fabsf(x)));
        float prob_o = sigmoidf(x);
        float p_t = fg ? prob_o : (1.0f - prob_o);
        float af  = fg ? 0.25f  : 0.75f;
        float om  = 1.0f - p_t;
        l_focal = ce_o * af * om * om;
        if (fg) { l_cnt = 1.0f; my_g = NM - (int)(key & 0xFFFFFFFFull); }
        else    l_neg = prob_o * sigmoidf(pm[w][lane][20]);
    }

    // deterministic compaction into u.l (align region is dead now)
    unsigned ballf = __ballot_sync(~0u, fg);
    if (lane == 0) u.l.scnt[w] = __popc(ballf);
    __syncthreads();   // also protects union transition align -> l
    if (t == 0) {
        u.l.sbase[0] = 0;
#pragma unroll
        for (int ww = 0; ww < 8; ww++) u.l.sbase[ww + 1] = u.l.sbase[ww] + u.l.scnt[ww];
    }
    __syncthreads();
    int tot = u.l.sbase[8];
    if (fg) {
        int slot = u.l.sbase[w] + __popc(ballf & ((1u << lane) - 1u));
        u.l.slist[slot] = (t << 5) | my_g;
    }
    __syncthreads();

    float ace = 0, aciou = 0, aiou = 0, apos = 0, adfl = 0;
    float4 m4 = (lane < 20) ? cm4_s[lane] : make_float4(0, 0, 0, 0);

    for (int i = w; i < tot; i += 8) {
        int e = u.l.slist[i];
        int tl_ = e >> 5;                 // owner thread index == local anchor index
        int nn = nbase + tl_;
        int g = e & 31;
        size_t off = (size_t)b * NA + nn;
        int lab = lab_s[g];
        float4 gb4 = gtb_s[g];
        float mx = pm[tl_ >> 5][tl_ & 31][20];

        // masked LSE over 80 classes, 20 lanes, coalesced float4 (L1/L2-hot)
        float4 s4 = (lane < 20) ? ((const float4*)(ps + off * NC))[lane]
                                : make_float4(0, 0, 0, 0);
        float es = 0.0f;
        es += (m4.x != 0.0f) ? expf(s4.x - mx) : 0.0f;
        es += (m4.y != 0.0f) ? expf(s4.y - mx) : 0.0f;
        es += (m4.z != 0.0f) ? expf(s4.z - mx) : 0.0f;
        es += (m4.w != 0.0f) ? expf(s4.w - mx) : 0.0f;
#pragma unroll
        for (int o = 16; o > 0; o >>= 1) es += __shfl_xor_sync(~0u, es, o);
        float lse = mx + logf(es);

        int sl = lab >> 2, sc = lab & 3;
        float c0 = __shfl_sync(~0u, s4.x, sl);
        float c1 = __shfl_sync(~0u, s4.y, sl);
        float c2v = __shfl_sync(~0u, s4.z, sl);
        float c3 = __shfl_sync(~0u, s4.w, sl);
        float slab = (sc == 0) ? c0 : (sc == 1) ? c1 : (sc == 2) ? c2v : c3;

        float prob_o = sigmoidf(pobj[off]);

        // IoU / CIoU (warp-uniform)
        float4 a4 = ((const float4*)pb)[off];
        float iou = iou_box(a4.x, a4.y, a4.z, a4.w, gb4.x, gb4.y, gb4.z, gb4.w);
        float cw2 = fmaxf(a4.z, gb4.z) - fminf(a4.x, gb4.x);
        float ch2 = fmaxf(a4.w, gb4.w) - fminf(a4.y, gb4.y);
        float c2 = cw2 * cw2 + ch2 * ch2 + 1e-7f;
        float dx = a4.x + a4.z - gb4.x - gb4.z;
        float dy = a4.y + a4.w - gb4.y - gb4.w;
        float rho2 = (dx * dx + dy * dy) * 0.25f;
        float w1 = a4.z - a4.x, h1 = a4.w - a4.y;
        float w2b = gb4.z - gb4.x, h2b = gb4.w - gb4.y;
        float dat = atanf(w2b / (h2b + 1e-7f)) - atanf(w1 / (h1 + 1e-7f));
        float v = (4.0f / (3.14159265358979323846f * 3.14159265358979323846f)) * dat * dat;
        float alpha = v / (v - iou + 1.0f + 1e-7f);
        float ciou = iou - rho2 / c2 - v * alpha;

        // DFL: 16 lanes hold 64 logits, 4-lane groups per bin
        float4 d4 = (lane < 16) ? ((const float4*)(bd + off * (4 * REG)))[lane]
                                : make_float4(0, 0, 0, 0);
        int j = (lane >> 2) & 3;
        float2 apc = ((const float2*)ap)[nn];
        float s = st[nn];
        float tj = (j == 0) ? (apc.x - gb4.x) / s :
                   (j == 1) ? (apc.y - gb4.y) / s :
                   (j == 2) ? (gb4.z - apc.x) / s :
                              (gb4.w - apc.y) / s;
        float tv = fminf(fmaxf(tj, 0.0f), (float)(REG - 1) - 0.01f);
        int tl = (int)tv;
        int tr = min(tl + 1, REG - 1);
        float wl = (float)tr - tv;
        float wr = 1.0f - wl;

        float lmax = fmaxf(fmaxf(d4.x, d4.y), fmaxf(d4.z, d4.w));
        lmax = fmaxf(lmax, __shfl_xor_sync(~0u, lmax, 1));
        lmax = fmaxf(lmax, __shfl_xor_sync(~0u, lmax, 2));
        float lsum = expf(d4.x - lmax) + expf(d4.y - lmax) +
                     expf(d4.z - lmax) + expf(d4.w - lmax);
        lsum += __shfl_xor_sync(~0u, lsum, 1);
        lsum += __shfl_xor_sync(~0u, lsum, 2);
        float lse2 = lmax + logf(lsum);

        int baseL = lane & ~3;
        int stl = baseL + (tl >> 2), str_ = baseL + (tr >> 2);
        float tlx = __shfl_sync(~0u, d4.x, stl), tly = __shfl_sync(~0u, d4.y, stl);
        float tlz = __shfl_sync(~0u, d4.z, stl), tlw = __shfl_sync(~0u, d4.w, stl);
        int cl = tl & 3;
        float vtl = (cl == 0) ? tlx : (cl == 1) ? tly : (cl == 2) ? tlz : tlw;
        float trx = __shfl_sync(~0u, d4.x, str_), try_ = __shfl_sync(~0u, d4.y, str_);
        float trz = __shfl_sync(~0u, d4.z, str_), trw = __shfl_sync(~0u, d4.w, str_);
        int cr = tr & 3;
        float vtr = (cr == 0) ? trx : (cr == 1) ? try_ : (cr == 2) ? trz : trw;
        float dbin = (lse2 - vtl) * wl + (lse2 - vtr) * wr;
        float dc = (lane < 16 && (lane & 3) == 0) ? dbin : 0.0f;
#pragma unroll
        for (int o = 16; o > 0; o >>= 1) dc += __shfl_xor_sync(~0u, dc, o);

        ace   += lse - slab;
        aciou += 1.0f - ciou;
        aiou  += iou;
        apos  += prob_o * sigmoidf(slab);
        adfl  += dc;
    }

    // block reduction: light (warp sums) + heavy (warp-uniform)
#pragma unroll
    for (int o = 16; o > 0; o >>= 1) {
        l_focal += __shfl_xor_sync(~0u, l_focal, o);
        l_cnt   += __shfl_xor_sync(~0u, l_cnt, o);
        l_neg   += __shfl_xor_sync(~0u, l_neg, o);
    }
    if (lane == 0) {
        u.l.wred[w][0] = l_focal; u.l.wred[w][1] = l_cnt; u.l.wred[w][2] = aciou;
        u.l.wred[w][3] = aiou;    u.l.wred[w][4] = ace;   u.l.wred[w][5] = adfl;
        u.l.wred[w][6] = apos;    u.l.wred[w][7] = l_neg;
    }
    __syncthreads();
    if (t < 8) {
        float s = 0.0f;
#pragma unroll
        for (int ww = 0; ww < 8; ww++) s += u.l.wred[ww][t];
        g_partial[b][chunk][t] = s;
    }

    // ---- global last block: final scalars ----
    __threadfence();
    __syncthreads();
    if (t == 0) is_last = (atomicAdd(&g_ctr_loss, 1) == CHUNKS * BATCH - 1);
    __syncthreads();
    if (!is_last) return;
    if (t == 0) {
        g_ctr_loss = 0;
#pragma unroll
        for (int i = 0; i < BATCH; i++) g_flag[i] = 0;   // all blocks passed their spin
    }
    __threadfence();

    if (t < BATCH * 8) {
        int b2 = t >> 3, q = t & 7;
        float s = 0.0f;
#pragma unroll
        for (int c = 0; c < CHUNKS; c++) s += g_partial[b2][c][q];
        u.l.img[b2][q] = s;
    }
    __syncthreads();
    if (t == 0) {
        float tot_obj = 0, tot_iou = 0, tot_match = 0, tot_dfl = 0;
        float tot_pos = 0, miou = 0, pos = 0, neg = 0;
        for (int b2 = 0; b2 < BATCH; b2++) {
            float cnt = u.l.img[b2][1];
            float cs = fmaxf(cnt, 1.0f);
            tot_obj   += u.l.img[b2][0] / (float)NA;
            tot_iou   += u.l.img[b2][2] / cs;
            tot_match += u.l.img[b2][4] / cs;
            tot_dfl   += u.l.img[b2][5] / (4.0f * cs);
            tot_pos   += cnt;
            miou += u.l.img[b2][3];
            pos  += u.l.img[b2][6];
            neg  += u.l.img[b2][7];
        }
        float tot_neg = (float)(BATCH * NA) - tot_pos;
        float nb = (float)BATCH;
        float loss = (tot_obj + tot_match + 7.5f * tot_iou + 1.5f * tot_dfl) / nb;
        out[0] = loss;
        out[1] = tot_obj / nb;
        out[2] = tot_match / nb;
        out[3] = tot_iou / nb;
        out[4] = tot_dfl / nb;
        out[5] = tot_pos;
        out[6] = tot_neg;
        out[7] = pos / fmaxf(tot_pos, 1.0f);
        out[8] = neg / fmaxf(tot_neg, 1.0f);
        out[9] = miou / fmaxf(tot_pos, 1.0f);
    }
}

// ---------------- launch ----------------
extern "C" void kernel_launch(void* const* d_in, const int* in_sizes, int n_in,
                              void* d_out, int out_size) {
    const float* pred_boxes    = (const float*)d_in[0];
    const float* pred_scores   = (const float*)d_in[1];
    const float* pred_obj      = (const float*)d_in[2];
    const float* anchor_points = (const float*)d_in[3];
    const float* stride_tensor = (const float*)d_in[4];
    const float* box_dist      = (const float*)d_in[5];
    const void*  class_mask    = d_in[6];
    const float* gt_boxes      = (const float*)d_in[7];
    const void*  gt_labels     = d_in[8];
    float* out = (float*)d_out;

    dim3 g(CHUNKS, BATCH);
    k_all<<<g, 256>>>(pred_boxes, pred_scores, pred_obj, anchor_points,
                      stride_tensor, box_dist, gt_boxes,
                      class_mask, gt_labels, out);
}

// round 11
// speedup vs baseline: 1.0598x; 1.0051x over previous
#include <cuda_runtime.h>
#include <cstdint>

#define BATCH 16
#define NA    8400
#define NC    80
#define NM    24
#define KTOP  13
#define REG   16
#define CH    256
#define CHUNKS 33   // ceil(8400/256)

// ---------------- device scratch ----------------
__device__ unsigned long long g_best[BATCH * NA];
__device__ unsigned long long g_cand[BATCH * NM * CHUNKS * KTOP];
__device__ float g_partial[BATCH][CHUNKS][8];
__device__ int   g_ctr_main[BATCH];   // zero-init; self-resetting
__device__ int   g_ctr_loss;          // zero-init; self-resetting
__device__ int   g_flag[BATCH];       // zero-init; self-resetting

// ---------------- helpers ----------------
__device__ __forceinline__ float sigmoidf(float x) { return 1.0f / (1.0f + expf(-x)); }

__device__ __forceinline__ float iou_box(float a0, float a1, float a2, float a3,
                                         float b0, float b1, float b2, float b3) {
    float lt0 = fmaxf(a0, b0), lt1 = fmaxf(a1, b1);
    float rb0 = fminf(a2, b2), rb1 = fminf(a3, b3);
    float w = fmaxf(rb0 - lt0, 0.0f), h = fmaxf(rb1 - lt1, 0.0f);
    float inter = w * h;
    float aa = fmaxf(a2 - a0, 0.0f) * fmaxf(a3 - a1, 0.0f);
    float ab = fmaxf(b2 - b0, 0.0f) * fmaxf(b3 - b1, 0.0f);
    return inter / (aa + ab - inter + 1e-7f);
}

struct LossSmem {
    int   slist[CH];
    float wred[8][8];
    int   scnt[8];
    int   sbase[9];
    float img[BATCH][8];
};

// ============ k_all: the whole loss in ONE kernel ============
__global__ __launch_bounds__(256, 4) void k_all(const float* __restrict__ pb,
                                                const float* __restrict__ ps,
                                                const float* __restrict__ pobj,
                                                const float* __restrict__ ap,
                                                const float* __restrict__ st,
                                                const float* __restrict__ bd,
                                                const float* __restrict__ gtb,
                                                const void* __restrict__ cm_raw,
                                                const void* __restrict__ lab_raw,
                                                float* __restrict__ out) {
    __shared__ float  cm_s[NC];
    __shared__ float4 cm4_s[20];
    __shared__ int    lab_s[NM];
    __shared__ int    val_s[NM];
    __shared__ float4 gtb_s[NM];
    __shared__ float  pm[8][32][21];   // [..][..][0:20)=lane partial max, [20]=anchor mx
    __shared__ union SmemU { float align[NM][CH]; LossSmem l; } u;
    __shared__ int    detf[2];
    __shared__ int    is_last;

    int chunk = blockIdx.x, b = blockIdx.y, t = threadIdx.x;
    int lane = t & 31, w = t >> 5;
    int nbase = chunk * CH;

    // ---- per-block parallel dtype detect (reads ~320 broadcast bytes) ----
    if (t == 0) { detf[0] = 0; detf[1] = 0; }
    __syncthreads();
    const unsigned* cw = (const unsigned*)cm_raw;
    if (t < 80 && cw[t] > 1u) atomicOr(&detf[0], 1);
    if (t < NM && ((const unsigned*)lab_raw)[b * NM + t] > 1000u) atomicOr(&detf[1], 1);
#pragma unroll 4
    for (int g = 0; g < NM; g++) u.align[g][t] = -1.0f;
    if (nbase + t < NA) g_best[b * NA + nbase + t] = 0ull;
    __syncthreads();
    int cmode = (cw[0] == 0x3F800000u) ? 0 : (detf[0] ? 2 : 1);
    int lmode = detf[1];

    if (t < NC) {
        float v;
        int i = b * NC + t;
        if (cmode == 0)      v = ((const float*)cm_raw)[i];
        else if (cmode == 1) v = (float)(((const int*)cm_raw)[i] != 0);
        else                 v = (float)(((const unsigned char*)cm_raw)[i] != 0);
        cm_s[t] = (v != 0.0f) ? 1.0f : 0.0f;
    }
    if (t < NM) {
        int lb = lmode ? (int)(((const float*)lab_raw)[b * NM + t])
                       : ((const int*)lab_raw)[b * NM + t];
        int labc = min(max(lb, 0), NC - 1);
        lab_s[t] = labc;
        val_s[t] = (lb >= 0 && lb < NC);
        gtb_s[t] = ((const float4*)gtb)[b * NM + t];
    }
    __syncthreads();
    if (t < NM) val_s[t] = val_s[t] && (cm_s[lab_s[t]] != 0.0f);
    if (t < 20) cm4_s[t] = ((const float4*)cm_s)[t];
    __syncthreads();

    int a0 = nbase + w * 32;
    int alim = min(32, NA - a0);          // warp-uniform

    // ---- Phase A: coalesced score read, lane-partial masked max -> smem ----
    if (lane < 20 && alim > 0) {
        const float4* row4 = (const float4*)(ps + ((size_t)b * NA + a0) * NC);
        float4 m4 = cm4_s[lane];
        if (alim == 32) {
#pragma unroll
            for (int a = 0; a < 32; a++) {
                float4 s4 = row4[(size_t)a * 20 + lane];
                float m = -1e30f;
                m = fmaxf(m, m4.x != 0.0f ? s4.x : -1e30f);
                m = fmaxf(m, m4.y != 0.0f ? s4.y : -1e30f);
                m = fmaxf(m, m4.z != 0.0f ? s4.z : -1e30f);
                m = fmaxf(m, m4.w != 0.0f ? s4.w : -1e30f);
                pm[w][a][lane] = m;
            }
        } else {
            for (int a = 0; a < alim; a++) {
                float4 s4 = row4[(size_t)a * 20 + lane];
                float m = -1e30f;
                m = fmaxf(m, m4.x != 0.0f ? s4.x : -1e30f);
                m = fmaxf(m, m4.y != 0.0f ? s4.y : -1e30f);
                m = fmaxf(m, m4.z != 0.0f ? s4.z : -1e30f);
                m = fmaxf(m, m4.w != 0.0f ? s4.w : -1e30f);
                pm[w][a][lane] = m;
            }
        }
    }
    __syncwarp();

    // ---- Phase B: per-lane reduce own anchor's 20 partials -> pm[w][a][20] ----
    if (lane < alim) {
        float m = -1e30f;
#pragma unroll
        for (int j = 0; j < 20; j++) m = fmaxf(m, pm[w][lane][j]);
        pm[w][lane][20] = m;
    }
    __syncwarp();

    // ---- Phase C: align; lane owns anchor, loop GTs ----
    int n = a0 + lane;
    if (n < NA && alim > 0) {
        float2 apc = ((const float2*)ap)[n];
        float4 pbx = ((const float4*)pb)[(size_t)b * NA + n];
        const float* srow = ps + ((size_t)b * NA + n) * NC;
#pragma unroll 4
        for (int g = 0; g < NM; g++) {
            float4 gbx = gtb_s[g];
            bool inside = val_s[g] && apc.x >= gbx.x && apc.x <= gbx.z &&
                          apc.y >= gbx.y && apc.y <= gbx.w;
            if (inside) {
                float iou = iou_box(pbx.x, pbx.y, pbx.z, pbx.w, gbx.x, gbx.y, gbx.z, gbx.w);
                float cls = sigmoidf(srow[lab_s[g]]);
                float i2 = iou * iou;
                u.align[g][w * 32 + lane] = cls * (i2 * i2 * i2);
            }
        }
    }
    __syncthreads();

    // ---- Phase D: local top-13; warp w handles GTs w, w+8, w+16 ----
#pragma unroll
    for (int gi = 0; gi < 3; gi++) {
        int g = w + gi * 8;
        unsigned long long key[8];
        unsigned ball[8];
        int base[8], tot = 0;
#pragma unroll
        for (int r = 0; r < 8; r++) {
            float v = u.align[g][lane + 32 * r];
            int nn = nbase + lane + 32 * r;
            key[r] = (v >= 0.0f)
                ? (((unsigned long long)__float_as_uint(v) << 32) | (unsigned)(0xFFFFFFFFu - nn))
                : 0ull;
            ball[r] = __ballot_sync(~0u, key[r] != 0ull);
            base[r] = tot;
            tot += __popc(ball[r]);
        }
        unsigned long long* outc = g_cand + (((size_t)b * NM + g) * CHUNKS + chunk) * KTOP;

        if (tot <= KTOP) {
            unsigned lt = (1u << lane) - 1u;
#pragma unroll
            for (int r = 0; r < 8; r++) {
                if (key[r] != 0ull) {
                    int slot = base[r] + __popc(ball[r] & lt);
                    outc[slot] = key[r];
                }
            }
            if (lane >= tot && lane < KTOP) outc[lane] = 0ull;
        } else {
            for (int k = 0; k < KTOP; k++) {
                unsigned long long lm = key[0]; int lr = 0;
#pragma unroll
                for (int r = 1; r < 8; r++) if (key[r] > lm) { lm = key[r]; lr = r; }
                unsigned long long wm = lm;
#pragma unroll
                for (int o = 16; o > 0; o >>= 1) {
                    unsigned long long oth = __shfl_xor_sync(~0u, wm, o);
                    if (oth > wm) wm = oth;
                }
                if (lm == wm) key[lr] = 0ull;
                if (lane == 0) outc[k] = wm;
            }
        }
    }

    // ---- per-batch arrival; last block merges + scatters + releases flag ----
    __threadfence();
    __syncthreads();
    if (t == 0) is_last = (atomicAdd(&g_ctr_main[b], 1) == CHUNKS - 1);
    __syncthreads();
    if (is_last) {
        if (t == 0) g_ctr_main[b] = 0;   // reset for next replay
        __threadfence();                 // acquire all blocks' g_cand writes
#pragma unroll
        for (int gi = 0; gi < 3; gi++) {
            int g = w + gi * 8;
            const unsigned long long* src = g_cand + ((size_t)b * NM + g) * CHUNKS * KTOP;
            unsigned long long key[14];
#pragma unroll
            for (int r = 0; r < 14; r++) {
                int e = lane + 32 * r;
                key[r] = (e < CHUNKS * KTOP) ? src[e] : 0ull;
            }
            unsigned pri = (unsigned)(NM - g);
            for (int k = 0; k < KTOP; k++) {
                unsigned long long lm = key[0]; int lr = 0;
#pragma unroll
                for (int r = 1; r < 14; r++) if (key[r] > lm) { lm = key[r]; lr = r; }
                unsigned long long wm = lm;
#pragma unroll
                for (int o = 16; o > 0; o >>= 1) {
                    unsigned long long oth = __shfl_xor_sync(~0u, wm, o);
                    if (oth > wm) wm = oth;
                }
                if (wm == 0ull) break;
                if (lm == wm) {
                    key[lr] = 0ull;
                    int nn = (int)(0xFFFFFFFFu - (unsigned)(wm & 0xFFFFFFFFull));
                    unsigned long long key2 = (wm & 0xFFFFFFFF00000000ull) | pri;
                    atomicMax(&g_best[b * NA + nn], key2);
                }
            }
        }
        __threadfence();
        __syncthreads();
        if (t == 0) atomicExch(&g_flag[b], 1);
    }

    // ---- wait for this batch's merge (all 528 blocks co-resident: single wave) ----
    if (t == 0) {
        while (atomicAdd(&g_flag[b], 0) == 0) __nanosleep(64);
    }
    __syncthreads();
    __threadfence();

    // ================= loss phase (same block, same chunk) =================
    float l_focal = 0.0f, l_cnt = 0.0f, l_neg = 0.0f;
    int my_g = 0;
    bool fg = false;
    if (n < NA) {   // n = a0 + lane = nbase + t
        unsigned long long key = g_best[b * NA + n];
        fg = (key != 0ull);
        float x = pobj[(size_t)b * NA + n];
        float tt = fg ? 1.0f : 0.0f;
        float ce_o = fmaxf(x, 0.0f) - x * tt + log1pf(expf(-fabsf(x)));
        float prob_o = sigmoidf(x);
        float p_t = fg ? prob_o : (1.0f - prob_o);
        float af  = fg ? 0.25f  : 0.75f;
        float om  = 1.0f - p_t;
        l_focal = ce_o * af * om * om;
        if (fg) { l_cnt = 1.0f; my_g = NM - (int)(key & 0xFFFFFFFFull); }
        else    l_neg = prob_o * sigmoidf(pm[w][lane][20]);
    }

    // deterministic compaction into u.l (align region is dead now)
    unsigned ballf = __ballot_sync(~0u, fg);
    if (lane == 0) u.l.scnt[w] = __popc(ballf);
    __syncthreads();   // also protects union transition align -> l
    if (t == 0) {
        u.l.sbase[0] = 0;
#pragma unroll
        for (int ww = 0; ww < 8; ww++) u.l.sbase[ww + 1] = u.l.sbase[ww] + u.l.scnt[ww];
    }
    __syncthreads();
    int tot = u.l.sbase[8];
    if (fg) {
        int slot = u.l.sbase[w] + __popc(ballf & ((1u << lane) - 1u));
        u.l.slist[slot] = (t << 5) | my_g;
    }
    __syncthreads();

    float ace = 0, aciou = 0, aiou = 0, apos = 0, adfl = 0;
    float4 m4 = (lane < 20) ? cm4_s[lane] : make_float4(0, 0, 0, 0);

    for (int i = w; i < tot; i += 8) {
        int e = u.l.slist[i];
        int tl_ = e >> 5;                 // owner thread index == local anchor index
        int nn = nbase + tl_;
        int g = e & 31;
        size_t off = (size_t)b * NA + nn;
        int lab = lab_s[g];
        float4 gb4 = gtb_s[g];
        float mx = pm[tl_ >> 5][tl_ & 31][20];

        // masked LSE over 80 classes, 20 lanes, coalesced float4 (L1/L2-hot)
        float4 s4 = (lane < 20) ? ((const float4*)(ps + off * NC))[lane]
                                : make_float4(0, 0, 0, 0);
        float es = 0.0f;
        es += (m4.x != 0.0f) ? expf(s4.x - mx) : 0.0f;
        es += (m4.y != 0.0f) ? expf(s4.y - mx) : 0.0f;
        es += (m4.z != 0.0f) ? expf(s4.z - mx) : 0.0f;
        es += (m4.w != 0.0f) ? expf(s4.w - mx) : 0.0f;
#pragma unroll
        for (int o = 16; o > 0; o >>= 1) es += __shfl_xor_sync(~0u, es, o);
        float lse = mx + logf(es);

        int sl = lab >> 2, sc = lab & 3;
        float c0 = __shfl_sync(~0u, s4.x, sl);
        float c1 = __shfl_sync(~0u, s4.y, sl);
        float c2v = __shfl_sync(~0u, s4.z, sl);
        float c3 = __shfl_sync(~0u, s4.w, sl);
        float slab = (sc == 0) ? c0 : (sc == 1) ? c1 : (sc == 2) ? c2v : c3;

        float prob_o = sigmoidf(pobj[off]);

        // IoU / CIoU (warp-uniform)
        float4 a4 = ((const float4*)pb)[off];
        float iou = iou_box(a4.x, a4.y, a4.z, a4.w, gb4.x, gb4.y, gb4.z, gb4.w);
        float cw2 = fmaxf(a4.z, gb4.z) - fminf(a4.x, gb4.x);
        float ch2 = fmaxf(a4.w, gb4.w) - fminf(a4.y, gb4.y);
        float c2 = cw2 * cw2 + ch2 * ch2 + 1e-7f;
        float dx = a4.x + a4.z - gb4.x - gb4.z;
        float dy = a4.y + a4.w - gb4.y - gb4.w;
        float rho2 = (dx * dx + dy * dy) * 0.25f;
        float w1 = a4.z - a4.x, h1 = a4.w - a4.y;
        float w2b = gb4.z - gb4.x, h2b = gb4.w - gb4.y;
        float dat = atanf(w2b / (h2b + 1e-7f)) - atanf(w1 / (h1 + 1e-7f));
        float v = (4.0f / (3.14159265358979323846f * 3.14159265358979323846f)) * dat * dat;
        float alpha = v / (v - iou + 1.0f + 1e-7f);
        float ciou = iou - rho2 / c2 - v * alpha;

        // DFL: 16 lanes hold 64 logits, 4-lane groups per bin
        float4 d4 = (lane < 16) ? ((const float4*)(bd + off * (4 * REG)))[lane]
                                : make_float4(0, 0, 0, 0);
        int j = (lane >> 2) & 3;
        float2 apc = ((const float2*)ap)[nn];
        float s = st[nn];
        float tj = (j == 0) ? (apc.x - gb4.x) / s :
                   (j == 1) ? (apc.y - gb4.y) / s :
                   (j == 2) ? (gb4.z - apc.x) / s :
                              (gb4.w - apc.y) / s;
        float tv = fminf(fmaxf(tj, 0.0f), (float)(REG - 1) - 0.01f);
        int tl = (int)tv;
        int tr = min(tl + 1, REG - 1);
        float wl = (float)tr - tv;
        float wr = 1.0f - wl;

        float lmax = fmaxf(fmaxf(d4.x, d4.y), fmaxf(d4.z, d4.w));
        lmax = fmaxf(lmax, __shfl_xor_sync(~0u, lmax, 1));
        lmax = fmaxf(lmax, __shfl_xor_sync(~0u, lmax, 2));
        float lsum = expf(d4.x - lmax) + expf(d4.y - lmax) +
                     expf(d4.z - lmax) + expf(d4.w - lmax);
        lsum += __shfl_xor_sync(~0u, lsum, 1);
        lsum += __shfl_xor_sync(~0u, lsum, 2);
        float lse2 = lmax + logf(lsum);

        int baseL = lane & ~3;
        int stl = baseL + (tl >> 2), str_ = baseL + (tr >> 2);
        float tlx = __shfl_sync(~0u, d4.x, stl), tly = __shfl_sync(~0u, d4.y, stl);
        float tlz = __shfl_sync(~0u, d4.z, stl), tlw = __shfl_sync(~0u, d4.w, stl);
        int cl = tl & 3;
        float vtl = (cl == 0) ? tlx : (cl == 1) ? tly : (cl == 2) ? tlz : tlw;
        float trx = __shfl_sync(~0u, d4.x, str_), try_ = __shfl_sync(~0u, d4.y, str_);
        float trz = __shfl_sync(~0u, d4.z, str_), trw = __shfl_sync(~0u, d4.w, str_);
        int cr = tr & 3;
        float vtr = (cr == 0) ? trx : (cr == 1) ? try_ : (cr == 2) ? trz : trw;
        float dbin = (lse2 - vtl) * wl + (lse2 - vtr) * wr;
        float dc = (lane < 16 && (lane & 3) == 0) ? dbin : 0.0f;
#pragma unroll
        for (int o = 16; o > 0; o >>= 1) dc += __shfl_xor_sync(~0u, dc, o);

        ace   += lse - slab;
        aciou += 1.0f - ciou;
        aiou  += iou;
        apos  += prob_o * sigmoidf(slab);
        adfl  += dc;
    }

    // block reduction: light (warp sums) + heavy (warp-uniform)
#pragma unroll
    for (int o = 16; o > 0; o >>= 1) {
        l_focal += __shfl_xor_sync(~0u, l_focal, o);
        l_cnt   += __shfl_xor_sync(~0u, l_cnt, o);
        l_neg   += __shfl_xor_sync(~0u, l_neg, o);
    }
    if (lane == 0) {
        u.l.wred[w][0] = l_focal; u.l.wred[w][1] = l_cnt; u.l.wred[w][2] = aciou;
        u.l.wred[w][3] = aiou;    u.l.wred[w][4] = ace;   u.l.wred[w][5] = adfl;
        u.l.wred[w][6] = apos;    u.l.wred[w][7] = l_neg;
    }
    __syncthreads();
    if (t < 8) {
        float s = 0.0f;
#pragma unroll
        for (int ww = 0; ww < 8; ww++) s += u.l.wred[ww][t];
        g_partial[b][chunk][t] = s;
    }

    // ---- global last block: final scalars ----
    __threadfence();
    __syncthreads();
    if (t == 0) is_last = (atomicAdd(&g_ctr_loss, 1) == CHUNKS * BATCH - 1);
    __syncthreads();
    if (!is_last) return;
    if (t == 0) {
        g_ctr_loss = 0;
#pragma unroll
        for (int i = 0; i < BATCH; i++) g_flag[i] = 0;   // all blocks passed their spin
    }
    __threadfence();

    if (t < BATCH * 8) {
        int b2 = t >> 3, q = t & 7;
        float s = 0.0f;
#pragma unroll
        for (int c = 0; c < CHUNKS; c++) s += g_partial[b2][c][q];
        u.l.img[b2][q] = s;
    }
    __syncthreads();
    if (t == 0) {
        float tot_obj = 0, tot_iou = 0, tot_match = 0, tot_dfl = 0;
        float tot_pos = 0, miou = 0, pos = 0, neg = 0;
        for (int b2 = 0; b2 < BATCH; b2++) {
            float cnt = u.l.img[b2][1];
            float cs = fmaxf(cnt, 1.0f);
            tot_obj   += u.l.img[b2][0] / (float)NA;
            tot_iou   += u.l.img[b2][2] / cs;
            tot_match += u.l.img[b2][4] / cs;
            tot_dfl   += u.l.img[b2][5] / (4.0f * cs);
            tot_pos   += cnt;
            miou += u.l.img[b2][3];
            pos  += u.l.img[b2][6];
            neg  += u.l.img[b2][7];
        }
        float tot_neg = (float)(BATCH * NA) - tot_pos;
        float nb = (float)BATCH;
        float loss = (tot_obj + tot_match + 7.5f * tot_iou + 1.5f * tot_dfl) / nb;
        out[0] = loss;
        out[1] = tot_obj / nb;
        out[2] = tot_match / nb;
        out[3] = tot_iou / nb;
        out[4] = tot_dfl / nb;
        out[5] = tot_pos;
        out[6] = tot_neg;
        out[7] = pos / fmaxf(tot_pos, 1.0f);
        out[8] = neg / fmaxf(tot_neg, 1.0f);
        out[9] = miou / fmaxf(tot_pos, 1.0f);
    }
}

// ---------------- launch ----------------
extern "C" void kernel_launch(void* const* d_in, const int* in_sizes, int n_in,
                              void* d_out, int out_size) {
    const float* pred_boxes    = (const float*)d_in[0];
    const float* pred_scores   = (const float*)d_in[1];
    const float* pred_obj      = (const float*)d_in[2];
    const float* anchor_points = (const float*)d_in[3];
    const float* stride_tensor = (const float*)d_in[4];
    const float* box_dist      = (const float*)d_in[5];
    const void*  class_mask    = d_in[6];
    const float* gt_boxes      = (const float*)d_in[7];
    const void*  gt_labels     = d_in[8];
    float* out = (float*)d_out;

    dim3 g(CHUNKS, BATCH);
    k_all<<<g, 256>>>(pred_boxes, pred_scores, pred_obj, anchor_points,
                      stride_tensor, box_dist, gt_boxes,
                      class_mask, gt_labels, out);
}